// round 6
// baseline (speedup 1.0000x reference)
#include <cuda_runtime.h>
#include <cuda_bf16.h>
#include <math.h>
#include <stdint.h>

// Problem constants
#define NB 8
#define NQ 8
#define HID 4096
#define NH 32
#define NKVH 8
#define NG 4
#define DH 128
#define LKV 4096
#define NSPLIT 16
#define MR 64                    // B*Q rows
#define SPLIT_LEN (LKV / NSPLIT) // 256
#define CS 32                    // keys per chunk
#define NCH (SPLIT_LEN / CS)     // 8
#define KSPLIT 8                 // GEMM k-split

// Scratch (device globals — no allocation allowed)
__device__ float g_part[KSPLIT * MR * HID];             // GEMM split-K partials (8MB)
__device__ float g_q[MR * HID];                         // roped+scaled Q, [bk][r][d]
__device__ float g_attn[MR * HID];                      // merged attn out [(b,qq)][h*128+d]
__device__ float g_po[NB * NKVH * NSPLIT * 32 * DH];    // partial O (unnormalized)
__device__ float g_pm[NB * NKVH * NSPLIT * 32];
__device__ float g_pl[NB * NKVH * NSPLIT * 32];
__device__ float g_cos[NB * 64];
__device__ float g_sin[NB * 64];

// ---------------------------------------------------------------------------
// bf16 hi/lo split helpers + m16n8k16 mma
// ---------------------------------------------------------------------------
__device__ __forceinline__ void split2(float x, float y, uint32_t& hi, uint32_t& lo) {
    __nv_bfloat16 hx = __float2bfloat16(x), hy = __float2bfloat16(y);
    float rx = x - __bfloat162float(hx);
    float ry = y - __bfloat162float(hy);
    __nv_bfloat16 lx = __float2bfloat16(rx), ly = __float2bfloat16(ry);
    __nv_bfloat162 h2 = __halves2bfloat162(hx, hy);
    __nv_bfloat162 l2 = __halves2bfloat162(lx, ly);
    hi = *reinterpret_cast<uint32_t*>(&h2);
    lo = *reinterpret_cast<uint32_t*>(&l2);
}

__device__ __forceinline__ void mma_bf16(float c[4],
                                         uint32_t a0, uint32_t a1, uint32_t a2, uint32_t a3,
                                         uint32_t b0, uint32_t b1) {
    asm volatile(
        "mma.sync.aligned.m16n8k16.row.col.f32.bf16.bf16.f32 "
        "{%0,%1,%2,%3}, {%4,%5,%6,%7}, {%8,%9}, {%0,%1,%2,%3};\n"
        : "+f"(c[0]), "+f"(c[1]), "+f"(c[2]), "+f"(c[3])
        : "r"(a0), "r"(a1), "r"(a2), "r"(a3), "r"(b0), "r"(b1));
}

// ---------------------------------------------------------------------------
// Kernel 1: dtype-detect position_ids, argmax row 0, cos/sin tables.
// ---------------------------------------------------------------------------
__global__ void rope_setup_kernel(const int* __restrict__ p32) {
    __shared__ int sv[256], si[256];
    __shared__ int s_is64, s_idx;
    int t = threadIdx.x;

    if (t == 0) {
        int is64 = 1;
        for (int i = 1; i < 64; i += 2)
            if (p32[i] != 0) { is64 = 0; break; }
        s_is64 = is64;
    }
    __syncthreads();
    const int is64 = s_is64;
    const int stride = is64 ? 2 : 1;

    int bv = -2147483647, bi = 0;
    for (int i = t; i < LKV; i += 256) {
        int v = p32[i * stride];
        if (v > bv) { bv = v; bi = i; }
    }
    sv[t] = bv; si[t] = bi;
    __syncthreads();
    for (int off = 128; off > 0; off >>= 1) {
        if (t < off) {
            if (sv[t + off] > sv[t] || (sv[t + off] == sv[t] && si[t + off] < si[t])) {
                sv[t] = sv[t + off]; si[t] = si[t + off];
            }
        }
        __syncthreads();
    }
    if (t == 0) s_idx = si[0];
    __syncthreads();
    const int idx = s_idx;

    for (int i = t; i < NB * 64; i += 256) {
        int b = i >> 6, j = i & 63;
        long long pv;
        if (is64) pv = ((const long long*)p32)[b * LKV + idx];
        else      pv = (long long)p32[b * LKV + idx];
        double ang = (double)pv * pow(10000.0, -(double)j / 64.0);
        g_cos[i] = (float)cos(ang);
        g_sin[i] = (float)sin(ang);
    }
}

// ---------------------------------------------------------------------------
// Tensor-core GEMM (bf16 3-pass, register-prefetch pipeline).
// part[ks][m][n] = sum_{k slice} A[m][k] * W[n][k]
// Grid: 64 x KSPLIT, 256 threads (8 warps). Warp: m-tile (w&3)*16, n-half (w>>2)*32.
// ---------------------------------------------------------------------------
#define GSTR 20
__global__ __launch_bounds__(256) void gemm_mma_kernel(
    const float* __restrict__ Aext, const float* __restrict__ W, int phase)
{
    const float* A = phase ? g_attn : Aext;

    __shared__ uint32_t Ah[64 * GSTR], Al[64 * GSTR];
    __shared__ uint32_t Wh[64 * GSTR], Wl[64 * GSTR];

    int t = threadIdx.x;
    int nb = blockIdx.x * 64;
    int ks = blockIdx.y;
    int k_begin = ks * (HID / KSPLIT);
    int k_end = k_begin + HID / KSPLIT;
    int w = t >> 5, lane = t & 31;
    int g = lane >> 2, tig = lane & 3;
    int wm = (w & 3) * 16;
    int wn = (w >> 2) * 32;

    float c[4][4] = {};
    float4 va[2], vw[2];

    // prologue prefetch
#pragma unroll
    for (int i = 0; i < 2; i++) {
        int f4 = t + i * 256;
        int row = f4 >> 3, kq = f4 & 7;
        va[i] = *(const float4*)(A + (size_t)row * HID + k_begin + kq * 4);
        vw[i] = *(const float4*)(W + (size_t)(nb + row) * HID + k_begin + kq * 4);
    }

    for (int kc0 = k_begin; kc0 < k_end; kc0 += 32) {
        __syncthreads();
#pragma unroll
        for (int i = 0; i < 2; i++) {
            int f4 = t + i * 256;
            int row = f4 >> 3, kq = f4 & 7;
            uint32_t h0, l0, h1, l1;
            split2(va[i].x, va[i].y, h0, l0);
            split2(va[i].z, va[i].w, h1, l1);
            *(uint2*)&Ah[row * GSTR + kq * 2] = make_uint2(h0, h1);
            *(uint2*)&Al[row * GSTR + kq * 2] = make_uint2(l0, l1);
            split2(vw[i].x, vw[i].y, h0, l0);
            split2(vw[i].z, vw[i].w, h1, l1);
            *(uint2*)&Wh[row * GSTR + kq * 2] = make_uint2(h0, h1);
            *(uint2*)&Wl[row * GSTR + kq * 2] = make_uint2(l0, l1);
        }
        __syncthreads();

        int kn2 = kc0 + 32;
        if (kn2 < k_end) {
#pragma unroll
            for (int i = 0; i < 2; i++) {
                int f4 = t + i * 256;
                int row = f4 >> 3, kq = f4 & 7;
                va[i] = *(const float4*)(A + (size_t)row * HID + kn2 + kq * 4);
                vw[i] = *(const float4*)(W + (size_t)(nb + row) * HID + kn2 + kq * 4);
            }
        }

#pragma unroll
        for (int kstep = 0; kstep < 2; kstep++) {
            int base = kstep * 8;
            uint32_t ah0 = Ah[(wm + g) * GSTR + base + tig];
            uint32_t ah1 = Ah[(wm + g + 8) * GSTR + base + tig];
            uint32_t ah2 = Ah[(wm + g) * GSTR + base + tig + 4];
            uint32_t ah3 = Ah[(wm + g + 8) * GSTR + base + tig + 4];
            uint32_t al0 = Al[(wm + g) * GSTR + base + tig];
            uint32_t al1 = Al[(wm + g + 8) * GSTR + base + tig];
            uint32_t al2 = Al[(wm + g) * GSTR + base + tig + 4];
            uint32_t al3 = Al[(wm + g + 8) * GSTR + base + tig + 4];
#pragma unroll
            for (int nt = 0; nt < 4; nt++) {
                int nrow = wn + nt * 8 + g;
                uint32_t bh0 = Wh[nrow * GSTR + base + tig];
                uint32_t bh1 = Wh[nrow * GSTR + base + tig + 4];
                uint32_t bl0 = Wl[nrow * GSTR + base + tig];
                uint32_t bl1 = Wl[nrow * GSTR + base + tig + 4];
                mma_bf16(c[nt], ah0, ah1, ah2, ah3, bh0, bh1);
                mma_bf16(c[nt], ah0, ah1, ah2, ah3, bl0, bl1);
                mma_bf16(c[nt], al0, al1, al2, al3, bh0, bh1);
            }
        }
    }

    float* P = g_part + (size_t)ks * MR * HID;
#pragma unroll
    for (int nt = 0; nt < 4; nt++) {
        int col = nb + wn + nt * 8 + tig * 2;
        int r0 = wm + g, r1 = wm + g + 8;
        P[r0 * HID + col] = c[nt][0]; P[r0 * HID + col + 1] = c[nt][1];
        P[r1 * HID + col] = c[nt][2]; P[r1 * HID + col + 1] = c[nt][3];
    }
}

// ---------------------------------------------------------------------------
// Reduce GEMM1 partials + RoPE + scale by 1/sqrt(D) + relayout into g_q.
// ---------------------------------------------------------------------------
__global__ void rope_reduce_kernel() {
    const float scl = 0.08838834764831845f;  // 1/sqrt(128)
    int i = blockIdx.x * 256 + threadIdx.x;
    int dj = i & 63;
    int h = (i >> 6) & 31;
    int m = i >> 11;
    int c1 = h * DH + dj, c2 = c1 + 64;
    float x = 0.f, o = 0.f;
#pragma unroll
    for (int ks = 0; ks < KSPLIT; ks++) {
        x += g_part[ks * MR * HID + m * HID + c1];
        o += g_part[ks * MR * HID + m * HID + c2];
    }
    int b = m >> 3, qq = m & 7;
    float cc = g_cos[b * 64 + dj], ss = g_sin[b * 64 + dj];
    float v1 = (x * cc - o * ss) * scl;
    float v2 = (o * cc + x * ss) * scl;
    int kvh = h >> 2, gg = h & 3;
    int r = gg * NQ + qq;
    int bk = b * NKVH + kvh;
    g_q[(bk * 32 + r) * DH + dj] = v1;
    g_q[(bk * 32 + r) * DH + dj + 64] = v2;
}

// ---------------------------------------------------------------------------
// Reduce GEMM2 partials into d_out.
// ---------------------------------------------------------------------------
__global__ void reduce_out_kernel(float* __restrict__ out) {
    int i = blockIdx.x * 256 + threadIdx.x;
    float s = 0.f;
#pragma unroll
    for (int ks = 0; ks < KSPLIT; ks++)
        s += g_part[ks * MR * HID + i];
    out[i] = s;
}

// ---------------------------------------------------------------------------
// Split-KV flash attention: 1024 blocks (64 bk x 16 splits), 256 thr (8 warps),
// CS=32 chunks, register-prefetch pipeline, conflict-free smem layouts.
// Q fragments hoisted to registers (loop-invariant) — removes ~1/3 of smem traffic.
// Warp roles: QK (m-half (w&1)*16) x (s-eighth (w>>1)*8);
//             PV (m-half) x (d-quarter (w>>1)*32).
// ---------------------------------------------------------------------------
#define QSTR 68    // Q/K row stride (64 words + 4 pad)
#define VSTR 17    // Vt row stride (16 spairs + 1)
#define SSTR 33    // score row stride
#define PSTR 17    // P row stride

#define OFF_QH 0
#define OFF_QL (OFF_QH + 32 * QSTR)          // 2176
#define OFF_KH (OFF_QL + 32 * QSTR)          // 4352
#define OFF_KL (OFF_KH + 32 * QSTR)          // 6528
#define OFF_VH (OFF_KL + 32 * QSTR)          // 8704
#define OFF_VL (OFF_VH + 128 * VSTR)         // 10880
#define OFF_SC (OFF_VL + 128 * VSTR)         // 13056
#define OFF_PH (OFF_SC + 32 * SSTR)          // 14112
#define OFF_PL (OFF_PH + 32 * PSTR)          // 14656
#define OFF_AUX (OFF_PL + 32 * PSTR)         // 15200
#define SMEM_WORDS (OFF_AUX + 96)            // 15296 words = 61184 B

__global__ __launch_bounds__(256) void attn_mma_kernel(
    const float* __restrict__ Kc, const float* __restrict__ Vc)
{
    extern __shared__ uint32_t sw[];
    uint32_t* Qh = sw + OFF_QH;
    uint32_t* Ql = sw + OFF_QL;
    uint32_t* Kh = sw + OFF_KH;
    uint32_t* Kl = sw + OFF_KL;
    uint32_t* Vh = sw + OFF_VH;
    uint32_t* Vl = sw + OFF_VL;
    float*    Sc = (float*)(sw + OFF_SC);
    uint32_t* Ph = sw + OFF_PH;
    uint32_t* Pl = sw + OFF_PL;
    float*    rm = (float*)(sw + OFF_AUX);
    float*    rl = rm + 32;
    float*    rs = rl + 32;

    int t = threadIdx.x;
    int w = t >> 5, lane = t & 31;
    int g = lane >> 2, tig = lane & 3;
    int sp = blockIdx.x & (NSPLIT - 1), bk = blockIdx.x >> 4;
    const float* Kb = Kc + (size_t)bk * LKV * DH;
    const float* Vb = Vc + (size_t)bk * LKV * DH;

    int qm = (w & 1) * 16;      // m-half
    int kn = (w >> 1) * 8;      // QK col base (8 cols per warp)
    int dB = (w >> 1) * 32;     // PV d base

    // stage Q (pre-scaled by 1/sqrt(D) in rope_reduce)
#pragma unroll
    for (int i = 0; i < 4; i++) {
        int f4 = t + i * 256;
        int row = f4 >> 5, q4 = f4 & 31;
        float4 v = *(const float4*)(g_q + (size_t)(bk * 32 + row) * DH + q4 * 4);
        uint32_t h0, l0, h1, l1;
        split2(v.x, v.y, h0, l0);
        split2(v.z, v.w, h1, l1);
        *(uint2*)&Qh[row * QSTR + q4 * 2] = make_uint2(h0, h1);
        *(uint2*)&Ql[row * QSTR + q4 * 2] = make_uint2(l0, l1);
    }
    if (t < 32) { rm[t] = -INFINITY; rl[t] = 0.f; }
    __syncthreads();

    // hoist loop-invariant Q fragments into registers (64 regs)
    uint32_t qh[8][4], ql[8][4];
#pragma unroll
    for (int ksd = 0; ksd < 8; ksd++) {
        int base = ksd * 8;
        qh[ksd][0] = Qh[(qm + g) * QSTR + base + tig];
        qh[ksd][1] = Qh[(qm + g + 8) * QSTR + base + tig];
        qh[ksd][2] = Qh[(qm + g) * QSTR + base + tig + 4];
        qh[ksd][3] = Qh[(qm + g + 8) * QSTR + base + tig + 4];
        ql[ksd][0] = Ql[(qm + g) * QSTR + base + tig];
        ql[ksd][1] = Ql[(qm + g + 8) * QSTR + base + tig];
        ql[ksd][2] = Ql[(qm + g) * QSTR + base + tig + 4];
        ql[ksd][3] = Ql[(qm + g + 8) * QSTR + base + tig + 4];
    }

    float o[4][4] = {};
    float4 kreg[4];
    float  vreg[16];

    int s_base = sp * SPLIT_LEN;

    // prologue: prefetch chunk 0
    {
#pragma unroll
        for (int i = 0; i < 4; i++) {
            int f4 = t + i * 256;
            int row = f4 >> 5, q4 = f4 & 31;
            kreg[i] = *(const float4*)(Kb + (size_t)(s_base + row) * DH + q4 * 4);
        }
#pragma unroll
        for (int i = 0; i < 2; i++) {
            int spair = w + 8 * i;
#pragma unroll
            for (int j = 0; j < 4; j++) {
                int d = lane + 32 * j;
                vreg[i * 8 + j * 2]     = Vb[(size_t)(s_base + 2 * spair) * DH + d];
                vreg[i * 8 + j * 2 + 1] = Vb[(size_t)(s_base + 2 * spair + 1) * DH + d];
            }
        }
    }

    for (int ch = 0; ch < NCH; ch++) {
        int sc0 = s_base + ch * CS;
        __syncthreads();   // prev PV done; smem K/V free

        // STS current chunk from registers (conflict-free)
#pragma unroll
        for (int i = 0; i < 4; i++) {
            int f4 = t + i * 256;
            int row = f4 >> 5, q4 = f4 & 31;
            uint32_t h0, l0, h1, l1;
            split2(kreg[i].x, kreg[i].y, h0, l0);
            split2(kreg[i].z, kreg[i].w, h1, l1);
            *(uint2*)&Kh[row * QSTR + q4 * 2] = make_uint2(h0, h1);
            *(uint2*)&Kl[row * QSTR + q4 * 2] = make_uint2(l0, l1);
        }
#pragma unroll
        for (int i = 0; i < 2; i++) {
            int spair = w + 8 * i;
#pragma unroll
            for (int j = 0; j < 4; j++) {
                int d = lane + 32 * j;
                uint32_t h, l;
                split2(vreg[i * 8 + j * 2], vreg[i * 8 + j * 2 + 1], h, l);
                Vh[d * VSTR + spair] = h;
                Vl[d * VSTR + spair] = l;
            }
        }
        __syncthreads();

        // prefetch next chunk
        if (ch + 1 < NCH) {
            int sn = sc0 + CS;
#pragma unroll
            for (int i = 0; i < 4; i++) {
                int f4 = t + i * 256;
                int row = f4 >> 5, q4 = f4 & 31;
                kreg[i] = *(const float4*)(Kb + (size_t)(sn + row) * DH + q4 * 4);
            }
#pragma unroll
            for (int i = 0; i < 2; i++) {
                int spair = w + 8 * i;
#pragma unroll
                for (int j = 0; j < 4; j++) {
                    int d = lane + 32 * j;
                    vreg[i * 8 + j * 2]     = Vb[(size_t)(sn + 2 * spair) * DH + d];
                    vreg[i * 8 + j * 2 + 1] = Vb[(size_t)(sn + 2 * spair + 1) * DH + d];
                }
            }
        }

        // QK^T: warp computes 16 q-rows x 8 s-cols (Q from registers)
        float s4[4] = {0.f, 0.f, 0.f, 0.f};
#pragma unroll
        for (int ksd = 0; ksd < 8; ksd++) {
            int base = ksd * 8;
            int srow = kn + g;
            uint32_t bh0 = Kh[srow * QSTR + base + tig];
            uint32_t bh1 = Kh[srow * QSTR + base + tig + 4];
            uint32_t bl0 = Kl[srow * QSTR + base + tig];
            uint32_t bl1 = Kl[srow * QSTR + base + tig + 4];
            mma_bf16(s4, qh[ksd][0], qh[ksd][1], qh[ksd][2], qh[ksd][3], bh0, bh1);
            mma_bf16(s4, qh[ksd][0], qh[ksd][1], qh[ksd][2], qh[ksd][3], bl0, bl1);
            mma_bf16(s4, ql[ksd][0], ql[ksd][1], ql[ksd][2], ql[ksd][3], bh0, bh1);
        }
        {
            int col = kn + tig * 2;
            int r0 = qm + g, r1 = qm + g + 8;
            int sg0 = sc0 + col, sg1 = sg0 + 1;
            float v00 = s4[0], v01 = s4[1], v10 = s4[2], v11 = s4[3];
            if (sg0 > 4088 + (r0 & 7)) v00 = -10000.f;
            if (sg1 > 4088 + (r0 & 7)) v01 = -10000.f;
            if (sg0 > 4088 + (r1 & 7)) v10 = -10000.f;
            if (sg1 > 4088 + (r1 & 7)) v11 = -10000.f;
            Sc[r0 * SSTR + col] = v00; Sc[r0 * SSTR + col + 1] = v01;
            Sc[r1 * SSTR + col] = v10; Sc[r1 * SSTR + col + 1] = v11;
        }
        __syncthreads();

        // online softmax: warp w owns rows w*4 .. w*4+3 (32 cols each)
#pragma unroll
        for (int k2 = 0; k2 < 4; k2++) {
            int rr = w * 4 + k2;
            float v = Sc[rr * SSTR + lane];
            float mx = v;
#pragma unroll
            for (int off = 16; off > 0; off >>= 1)
                mx = fmaxf(mx, __shfl_xor_sync(0xffffffffu, mx, off));
            float mprev = rm[rr];
            float mnew = fmaxf(mprev, mx);
            float p = __expf(v - mnew);
            float ls = p;
#pragma unroll
            for (int off = 16; off > 0; off >>= 1)
                ls += __shfl_xor_sync(0xffffffffu, ls, off);
            float pe = __shfl_sync(0xffffffffu, p, (lane & 15) * 2);
            float po = __shfl_sync(0xffffffffu, p, (lane & 15) * 2 + 1);
            if (lane < 16) {
                uint32_t hh, ll;
                split2(pe, po, hh, ll);
                Ph[rr * PSTR + lane] = hh;
                Pl[rr * PSTR + lane] = ll;
            }
            if (lane == 0) {
                float f = __expf(mprev - mnew);
                rl[rr] = rl[rr] * f + ls;
                rm[rr] = mnew;
                rs[rr] = f;
            }
        }
        __syncthreads();

        // rescale + PV: warp computes 16 q-rows x 32 d-cols
        float f0 = rs[qm + g], f1 = rs[qm + g + 8];
#pragma unroll
        for (int nt = 0; nt < 4; nt++) {
            o[nt][0] *= f0; o[nt][1] *= f0;
            o[nt][2] *= f1; o[nt][3] *= f1;
        }
#pragma unroll
        for (int kstep = 0; kstep < 2; kstep++) {
            int base = kstep * 8;
            uint32_t ah0 = Ph[(qm + g) * PSTR + base + tig];
            uint32_t ah1 = Ph[(qm + g + 8) * PSTR + base + tig];
            uint32_t ah2 = Ph[(qm + g) * PSTR + base + tig + 4];
            uint32_t ah3 = Ph[(qm + g + 8) * PSTR + base + tig + 4];
            uint32_t al0 = Pl[(qm + g) * PSTR + base + tig];
            uint32_t al1 = Pl[(qm + g + 8) * PSTR + base + tig];
            uint32_t al2 = Pl[(qm + g) * PSTR + base + tig + 4];
            uint32_t al3 = Pl[(qm + g + 8) * PSTR + base + tig + 4];
#pragma unroll
            for (int nt = 0; nt < 4; nt++) {
                int drow = dB + nt * 8 + g;
                uint32_t bh0 = Vh[drow * VSTR + base + tig];
                uint32_t bh1 = Vh[drow * VSTR + base + tig + 4];
                uint32_t bl0 = Vl[drow * VSTR + base + tig];
                uint32_t bl1 = Vl[drow * VSTR + base + tig + 4];
                mma_bf16(o[nt], ah0, ah1, ah2, ah3, bh0, bh1);
                mma_bf16(o[nt], ah0, ah1, ah2, ah3, bl0, bl1);
                mma_bf16(o[nt], al0, al1, al2, al3, bh0, bh1);
            }
        }
    }

    int pbase = (bk * NSPLIT + sp) * 32;
    if (t < 32) { g_pm[pbase + t] = rm[t]; g_pl[pbase + t] = rl[t]; }
#pragma unroll
    for (int nt = 0; nt < 4; nt++) {
        int col = dB + nt * 8 + tig * 2;
        int r0 = qm + g, r1 = qm + g + 8;
        g_po[(size_t)(pbase + r0) * DH + col]     = o[nt][0];
        g_po[(size_t)(pbase + r0) * DH + col + 1] = o[nt][1];
        g_po[(size_t)(pbase + r1) * DH + col]     = o[nt][2];
        g_po[(size_t)(pbase + r1) * DH + col + 1] = o[nt][3];
    }
}

// ---------------------------------------------------------------------------
// Merge split partials (log-sum-exp) + relayout to [(b,qq)][h*128+d]
// ---------------------------------------------------------------------------
__global__ void merge_kernel() {
    int i = blockIdx.x * 256 + threadIdx.x;   // 0 .. 262143
    int d = i & 127;
    int rg = i >> 7;
    int bk = rg >> 5, r = rg & 31;
    float mv[NSPLIT];
    float mmax = -INFINITY;
#pragma unroll
    for (int sp = 0; sp < NSPLIT; sp++) {
        mv[sp] = g_pm[(bk * NSPLIT + sp) * 32 + r];
        mmax = fmaxf(mmax, mv[sp]);
    }
    float num = 0.f, den = 0.f;
#pragma unroll
    for (int sp = 0; sp < NSPLIT; sp++) {
        float wgt = __expf(mv[sp] - mmax);
        num += wgt * g_po[(size_t)((bk * NSPLIT + sp) * 32 + r) * DH + d];
        den += wgt * g_pl[(bk * NSPLIT + sp) * 32 + r];
    }
    float val = num / den;
    int b = bk >> 3, kvh = bk & 7, gg = r >> 3, qq = r & 7;
    int h = kvh * NG + gg;
    g_attn[(b * NQ + qq) * HID + h * DH + d] = val;
}

// ---------------------------------------------------------------------------
// kernel_launch
// ---------------------------------------------------------------------------
extern "C" void kernel_launch(void* const* d_in, const int* in_sizes, int n_in,
                              void* d_out, int out_size) {
    (void)in_sizes; (void)n_in; (void)out_size;
    const float* hidden = (const float*)d_in[0];
    const int* pos = (const int*)d_in[1];
    const float* kc = (const float*)d_in[2];
    const float* vc = (const float*)d_in[3];
    const float* qw = (const float*)d_in[5];
    const float* ow = (const float*)d_in[6];
    float* out = (float*)d_out;

    static int attr_done = 0;
    if (!attr_done) {
        cudaFuncSetAttribute(attn_mma_kernel,
                             cudaFuncAttributeMaxDynamicSharedMemorySize,
                             SMEM_WORDS * 4);
        attr_done = 1;
    }

    rope_setup_kernel<<<1, 256>>>(pos);
    gemm_mma_kernel<<<dim3(HID / 64, KSPLIT), 256>>>(hidden, qw, 0);
    rope_reduce_kernel<<<512, 256>>>();
    attn_mma_kernel<<<64 * NSPLIT, 256, SMEM_WORDS * 4>>>(kc, vc);
    merge_kernel<<<1024, 256>>>();
    gemm_mma_kernel<<<dim3(HID / 64, KSPLIT), 256>>>(nullptr, ow, 1);
    reduce_out_kernel<<<1024, 256>>>(out);
}

// round 7
// speedup vs baseline: 1.0513x; 1.0513x over previous
#include <cuda_runtime.h>
#include <cuda_bf16.h>
#include <math.h>
#include <stdint.h>

// Problem constants
#define NB 8
#define NQ 8
#define HID 4096
#define NH 32
#define NKVH 8
#define NG 4
#define DH 128
#define LKV 4096
#define NSPLIT 16
#define MR 64                    // B*Q rows
#define SPLIT_LEN (LKV / NSPLIT) // 256
#define CS 32                    // keys per chunk
#define NCH (SPLIT_LEN / CS)     // 8
#define KSPLIT 8                 // GEMM k-split

// Scratch (device globals — no allocation allowed)
__device__ float g_part[KSPLIT * MR * HID];             // GEMM split-K partials (8MB)
__device__ float g_q[MR * HID];                         // roped+scaled Q, [bk][r][d]
__device__ uint32_t g_ah[MR * HID / 2];                 // packed bf16-hi A operand
__device__ uint32_t g_al[MR * HID / 2];                 // packed bf16-lo A operand
__device__ float g_po[NB * NKVH * NSPLIT * 32 * DH];    // partial O (unnormalized)
__device__ float g_pm[NB * NKVH * NSPLIT * 32];
__device__ float g_pl[NB * NKVH * NSPLIT * 32];
__device__ float g_cos[NB * 64];
__device__ float g_sin[NB * 64];

// ---------------------------------------------------------------------------
// Fast bf16 hi/lo split (6 instr / 2 elements) + m16n8k16 mma
// hi = packed bf16(x)|bf16(y) (x in low half), lo = packed remainder.
// ---------------------------------------------------------------------------
__device__ __forceinline__ void split2(float x, float y, uint32_t& hi, uint32_t& lo) {
    asm("cvt.rn.bf16x2.f32 %0, %1, %2;" : "=r"(hi) : "f"(y), "f"(x));
    float hx = __uint_as_float(hi << 16);
    float hy = __uint_as_float(hi & 0xFFFF0000u);
    float lx = x - hx, ly = y - hy;
    asm("cvt.rn.bf16x2.f32 %0, %1, %2;" : "=r"(lo) : "f"(ly), "f"(lx));
}

__device__ __forceinline__ void mma_bf16(float c[4],
                                         uint32_t a0, uint32_t a1, uint32_t a2, uint32_t a3,
                                         uint32_t b0, uint32_t b1) {
    asm volatile(
        "mma.sync.aligned.m16n8k16.row.col.f32.bf16.bf16.f32 "
        "{%0,%1,%2,%3}, {%4,%5,%6,%7}, {%8,%9}, {%0,%1,%2,%3};\n"
        : "+f"(c[0]), "+f"(c[1]), "+f"(c[2]), "+f"(c[3])
        : "r"(a0), "r"(a1), "r"(a2), "r"(a3), "r"(b0), "r"(b1));
}

// ---------------------------------------------------------------------------
// Kernel 1: dtype-detect position_ids, argmax row 0, cos/sin tables.
// ---------------------------------------------------------------------------
__global__ void rope_setup_kernel(const int* __restrict__ p32) {
    __shared__ int sv[256], si[256];
    __shared__ int s_is64, s_idx;
    int t = threadIdx.x;

    if (t == 0) {
        int is64 = 1;
        for (int i = 1; i < 64; i += 2)
            if (p32[i] != 0) { is64 = 0; break; }
        s_is64 = is64;
    }
    __syncthreads();
    const int is64 = s_is64;
    const int stride = is64 ? 2 : 1;

    int bv = -2147483647, bi = 0;
    for (int i = t; i < LKV; i += 256) {
        int v = p32[i * stride];
        if (v > bv) { bv = v; bi = i; }
    }
    sv[t] = bv; si[t] = bi;
    __syncthreads();
    for (int off = 128; off > 0; off >>= 1) {
        if (t < off) {
            if (sv[t + off] > sv[t] || (sv[t + off] == sv[t] && si[t + off] < si[t])) {
                sv[t] = sv[t + off]; si[t] = si[t + off];
            }
        }
        __syncthreads();
    }
    if (t == 0) s_idx = si[0];
    __syncthreads();
    const int idx = s_idx;

    for (int i = t; i < NB * 64; i += 256) {
        int b = i >> 6, j = i & 63;
        long long pv;
        if (is64) pv = ((const long long*)p32)[b * LKV + idx];
        else      pv = (long long)p32[b * LKV + idx];
        double ang = (double)pv * pow(10000.0, -(double)j / 64.0);
        g_cos[i] = (float)cos(ang);
        g_sin[i] = (float)sin(ang);
    }
}

// ---------------------------------------------------------------------------
// Pack hidden_states (A of GEMM1) into bf16 hi/lo once.
// 65536 float4 tasks, grid 256 x 256.
// ---------------------------------------------------------------------------
__global__ void pack_a_kernel(const float* __restrict__ A) {
    int i = blockIdx.x * 256 + threadIdx.x;   // 0..65535
    float4 v = *(const float4*)(A + (size_t)i * 4);
    uint32_t h0, l0, h1, l1;
    split2(v.x, v.y, h0, l0);
    split2(v.z, v.w, h1, l1);
    *(uint2*)&g_ah[i * 2] = make_uint2(h0, h1);
    *(uint2*)&g_al[i * 2] = make_uint2(l0, l1);
}

// ---------------------------------------------------------------------------
// Tensor-core GEMM (bf16 3-pass, register-prefetch pipeline).
// A pre-packed in g_ah/g_al (no in-kernel A conversion).
// part[ks][m][n] = sum_{k slice} A[m][k] * W[n][k]
// Grid: 64 x KSPLIT, 256 threads (8 warps). Warp: m-tile (w&3)*16, n-half (w>>2)*32.
// ---------------------------------------------------------------------------
#define GSTR 20
__global__ __launch_bounds__(256) void gemm_mma_kernel(const float* __restrict__ W)
{
    __shared__ uint32_t Ah[64 * GSTR], Al[64 * GSTR];
    __shared__ uint32_t Wh[64 * GSTR], Wl[64 * GSTR];

    int t = threadIdx.x;
    int nb = blockIdx.x * 64;
    int ks = blockIdx.y;
    int k_begin = ks * (HID / KSPLIT);
    int k_end = k_begin + HID / KSPLIT;
    int w = t >> 5, lane = t & 31;
    int g = lane >> 2, tig = lane & 3;
    int wm = (w & 3) * 16;
    int wn = (w >> 2) * 32;

    // A-load mapping: row = t>>2, q = t&3 (4 u32 per thread per buffer)
    int arow = t >> 2, aq = t & 3;

    float c[4][4] = {};
    uint4 pah, pal;
    float4 vw[2];

    // prologue prefetch
    pah = *(const uint4*)&g_ah[arow * (HID / 2) + k_begin / 2 + aq * 4];
    pal = *(const uint4*)&g_al[arow * (HID / 2) + k_begin / 2 + aq * 4];
#pragma unroll
    for (int i = 0; i < 2; i++) {
        int f4 = t + i * 256;
        int row = f4 >> 3, kq = f4 & 7;
        vw[i] = *(const float4*)(W + (size_t)(nb + row) * HID + k_begin + kq * 4);
    }

    for (int kc0 = k_begin; kc0 < k_end; kc0 += 32) {
        __syncthreads();
        *(uint4*)&Ah[arow * GSTR + aq * 4] = pah;
        *(uint4*)&Al[arow * GSTR + aq * 4] = pal;
#pragma unroll
        for (int i = 0; i < 2; i++) {
            int f4 = t + i * 256;
            int row = f4 >> 3, kq = f4 & 7;
            uint32_t h0, l0, h1, l1;
            split2(vw[i].x, vw[i].y, h0, l0);
            split2(vw[i].z, vw[i].w, h1, l1);
            *(uint2*)&Wh[row * GSTR + kq * 2] = make_uint2(h0, h1);
            *(uint2*)&Wl[row * GSTR + kq * 2] = make_uint2(l0, l1);
        }
        __syncthreads();

        int kn2 = kc0 + 32;
        if (kn2 < k_end) {
            pah = *(const uint4*)&g_ah[arow * (HID / 2) + kn2 / 2 + aq * 4];
            pal = *(const uint4*)&g_al[arow * (HID / 2) + kn2 / 2 + aq * 4];
#pragma unroll
            for (int i = 0; i < 2; i++) {
                int f4 = t + i * 256;
                int row = f4 >> 3, kq = f4 & 7;
                vw[i] = *(const float4*)(W + (size_t)(nb + row) * HID + kn2 + kq * 4);
            }
        }

#pragma unroll
        for (int kstep = 0; kstep < 2; kstep++) {
            int base = kstep * 8;
            uint32_t ah0 = Ah[(wm + g) * GSTR + base + tig];
            uint32_t ah1 = Ah[(wm + g + 8) * GSTR + base + tig];
            uint32_t ah2 = Ah[(wm + g) * GSTR + base + tig + 4];
            uint32_t ah3 = Ah[(wm + g + 8) * GSTR + base + tig + 4];
            uint32_t al0 = Al[(wm + g) * GSTR + base + tig];
            uint32_t al1 = Al[(wm + g + 8) * GSTR + base + tig];
            uint32_t al2 = Al[(wm + g) * GSTR + base + tig + 4];
            uint32_t al3 = Al[(wm + g + 8) * GSTR + base + tig + 4];
#pragma unroll
            for (int nt = 0; nt < 4; nt++) {
                int nrow = wn + nt * 8 + g;
                uint32_t bh0 = Wh[nrow * GSTR + base + tig];
                uint32_t bh1 = Wh[nrow * GSTR + base + tig + 4];
                uint32_t bl0 = Wl[nrow * GSTR + base + tig];
                uint32_t bl1 = Wl[nrow * GSTR + base + tig + 4];
                mma_bf16(c[nt], ah0, ah1, ah2, ah3, bh0, bh1);
                mma_bf16(c[nt], ah0, ah1, ah2, ah3, bl0, bl1);
                mma_bf16(c[nt], al0, al1, al2, al3, bh0, bh1);
            }
        }
    }

    float* P = g_part + (size_t)ks * MR * HID;
#pragma unroll
    for (int nt = 0; nt < 4; nt++) {
        int col = nb + wn + nt * 8 + tig * 2;
        int r0 = wm + g, r1 = wm + g + 8;
        P[r0 * HID + col] = c[nt][0]; P[r0 * HID + col + 1] = c[nt][1];
        P[r1 * HID + col] = c[nt][2]; P[r1 * HID + col + 1] = c[nt][3];
    }
}

// ---------------------------------------------------------------------------
// Reduce GEMM1 partials + RoPE + scale by 1/sqrt(D) + relayout into g_q.
// ---------------------------------------------------------------------------
__global__ void rope_reduce_kernel() {
    const float scl = 0.08838834764831845f;  // 1/sqrt(128)
    int i = blockIdx.x * 256 + threadIdx.x;
    int dj = i & 63;
    int h = (i >> 6) & 31;
    int m = i >> 11;
    int c1 = h * DH + dj, c2 = c1 + 64;
    float x = 0.f, o = 0.f;
#pragma unroll
    for (int ks = 0; ks < KSPLIT; ks++) {
        x += g_part[ks * MR * HID + m * HID + c1];
        o += g_part[ks * MR * HID + m * HID + c2];
    }
    int b = m >> 3, qq = m & 7;
    float cc = g_cos[b * 64 + dj], ss = g_sin[b * 64 + dj];
    float v1 = (x * cc - o * ss) * scl;
    float v2 = (o * cc + x * ss) * scl;
    int kvh = h >> 2, gg = h & 3;
    int r = gg * NQ + qq;
    int bk = b * NKVH + kvh;
    g_q[(bk * 32 + r) * DH + dj] = v1;
    g_q[(bk * 32 + r) * DH + dj + 64] = v2;
}

// ---------------------------------------------------------------------------
// Reduce GEMM2 partials into d_out.
// ---------------------------------------------------------------------------
__global__ void reduce_out_kernel(float* __restrict__ out) {
    int i = blockIdx.x * 256 + threadIdx.x;
    float s = 0.f;
#pragma unroll
    for (int ks = 0; ks < KSPLIT; ks++)
        s += g_part[ks * MR * HID + i];
    out[i] = s;
}

// ---------------------------------------------------------------------------
// Split-KV flash attention (round-5 config: 2 CTAs/SM, Q frags from smem).
// 1024 blocks (64 bk x 16 splits), 256 thr (8 warps), CS=32 chunks,
// register-prefetch pipeline, conflict-free smem layouts.
// ---------------------------------------------------------------------------
#define QSTR 68    // Q/K row stride (64 words + 4 pad)
#define VSTR 17    // Vt row stride (16 spairs + 1)
#define SSTR 33    // score row stride
#define PSTR 17    // P row stride

#define OFF_QH 0
#define OFF_QL (OFF_QH + 32 * QSTR)          // 2176
#define OFF_KH (OFF_QL + 32 * QSTR)          // 4352
#define OFF_KL (OFF_KH + 32 * QSTR)          // 6528
#define OFF_VH (OFF_KL + 32 * QSTR)          // 8704
#define OFF_VL (OFF_VH + 128 * VSTR)         // 10880
#define OFF_SC (OFF_VL + 128 * VSTR)         // 13056
#define OFF_PH (OFF_SC + 32 * SSTR)          // 14112
#define OFF_PL (OFF_PH + 32 * PSTR)          // 14656
#define OFF_AUX (OFF_PL + 32 * PSTR)         // 15200
#define SMEM_WORDS (OFF_AUX + 96)            // 15296 words = 61184 B

__global__ __launch_bounds__(256, 2) void attn_mma_kernel(
    const float* __restrict__ Kc, const float* __restrict__ Vc)
{
    extern __shared__ uint32_t sw[];
    uint32_t* Qh = sw + OFF_QH;
    uint32_t* Ql = sw + OFF_QL;
    uint32_t* Kh = sw + OFF_KH;
    uint32_t* Kl = sw + OFF_KL;
    uint32_t* Vh = sw + OFF_VH;
    uint32_t* Vl = sw + OFF_VL;
    float*    Sc = (float*)(sw + OFF_SC);
    uint32_t* Ph = sw + OFF_PH;
    uint32_t* Pl = sw + OFF_PL;
    float*    rm = (float*)(sw + OFF_AUX);
    float*    rl = rm + 32;
    float*    rs = rl + 32;

    int t = threadIdx.x;
    int w = t >> 5, lane = t & 31;
    int g = lane >> 2, tig = lane & 3;
    int sp = blockIdx.x & (NSPLIT - 1), bk = blockIdx.x >> 4;
    const float* Kb = Kc + (size_t)bk * LKV * DH;
    const float* Vb = Vc + (size_t)bk * LKV * DH;

    int qm = (w & 1) * 16;      // m-half
    int kn = (w >> 1) * 8;      // QK col base (8 cols per warp)
    int dB = (w >> 1) * 32;     // PV d base

    // stage Q (pre-scaled by 1/sqrt(D) in rope_reduce)
#pragma unroll
    for (int i = 0; i < 4; i++) {
        int f4 = t + i * 256;
        int row = f4 >> 5, q4 = f4 & 31;
        float4 v = *(const float4*)(g_q + (size_t)(bk * 32 + row) * DH + q4 * 4);
        uint32_t h0, l0, h1, l1;
        split2(v.x, v.y, h0, l0);
        split2(v.z, v.w, h1, l1);
        *(uint2*)&Qh[row * QSTR + q4 * 2] = make_uint2(h0, h1);
        *(uint2*)&Ql[row * QSTR + q4 * 2] = make_uint2(l0, l1);
    }
    if (t < 32) { rm[t] = -INFINITY; rl[t] = 0.f; }

    float o[4][4] = {};
    float4 kreg[4];
    float  vreg[16];

    int s_base = sp * SPLIT_LEN;

    // prologue: prefetch chunk 0
    {
#pragma unroll
        for (int i = 0; i < 4; i++) {
            int f4 = t + i * 256;
            int row = f4 >> 5, q4 = f4 & 31;
            kreg[i] = *(const float4*)(Kb + (size_t)(s_base + row) * DH + q4 * 4);
        }
#pragma unroll
        for (int i = 0; i < 2; i++) {
            int spair = w + 8 * i;
#pragma unroll
            for (int j = 0; j < 4; j++) {
                int d = lane + 32 * j;
                vreg[i * 8 + j * 2]     = Vb[(size_t)(s_base + 2 * spair) * DH + d];
                vreg[i * 8 + j * 2 + 1] = Vb[(size_t)(s_base + 2 * spair + 1) * DH + d];
            }
        }
    }

    for (int ch = 0; ch < NCH; ch++) {
        int sc0 = s_base + ch * CS;
        __syncthreads();   // prev PV done; smem K/V free (covers Q staging on first iter)

        // STS current chunk from registers (conflict-free)
#pragma unroll
        for (int i = 0; i < 4; i++) {
            int f4 = t + i * 256;
            int row = f4 >> 5, q4 = f4 & 31;
            uint32_t h0, l0, h1, l1;
            split2(kreg[i].x, kreg[i].y, h0, l0);
            split2(kreg[i].z, kreg[i].w, h1, l1);
            *(uint2*)&Kh[row * QSTR + q4 * 2] = make_uint2(h0, h1);
            *(uint2*)&Kl[row * QSTR + q4 * 2] = make_uint2(l0, l1);
        }
#pragma unroll
        for (int i = 0; i < 2; i++) {
            int spair = w + 8 * i;
#pragma unroll
            for (int j = 0; j < 4; j++) {
                int d = lane + 32 * j;
                uint32_t h, l;
                split2(vreg[i * 8 + j * 2], vreg[i * 8 + j * 2 + 1], h, l);
                Vh[d * VSTR + spair] = h;
                Vl[d * VSTR + spair] = l;
            }
        }
        __syncthreads();

        // prefetch next chunk (consumed next iteration -> latency hidden)
        if (ch + 1 < NCH) {
            int sn = sc0 + CS;
#pragma unroll
            for (int i = 0; i < 4; i++) {
                int f4 = t + i * 256;
                int row = f4 >> 5, q4 = f4 & 31;
                kreg[i] = *(const float4*)(Kb + (size_t)(sn + row) * DH + q4 * 4);
            }
#pragma unroll
            for (int i = 0; i < 2; i++) {
                int spair = w + 8 * i;
#pragma unroll
                for (int j = 0; j < 4; j++) {
                    int d = lane + 32 * j;
                    vreg[i * 8 + j * 2]     = Vb[(size_t)(sn + 2 * spair) * DH + d];
                    vreg[i * 8 + j * 2 + 1] = Vb[(size_t)(sn + 2 * spair + 1) * DH + d];
                }
            }
        }

        // QK^T: warp computes 16 q-rows x 8 s-cols
        float s4[4] = {0.f, 0.f, 0.f, 0.f};
#pragma unroll
        for (int ksd = 0; ksd < 8; ksd++) {
            int base = ksd * 8;
            int srow = kn + g;
            uint32_t ah0 = Qh[(qm + g) * QSTR + base + tig];
            uint32_t ah1 = Qh[(qm + g + 8) * QSTR + base + tig];
            uint32_t ah2 = Qh[(qm + g) * QSTR + base + tig + 4];
            uint32_t ah3 = Qh[(qm + g + 8) * QSTR + base + tig + 4];
            uint32_t al0 = Ql[(qm + g) * QSTR + base + tig];
            uint32_t al1 = Ql[(qm + g + 8) * QSTR + base + tig];
            uint32_t al2 = Ql[(qm + g) * QSTR + base + tig + 4];
            uint32_t al3 = Ql[(qm + g + 8) * QSTR + base + tig + 4];
            uint32_t bh0 = Kh[srow * QSTR + base + tig];
            uint32_t bh1 = Kh[srow * QSTR + base + tig + 4];
            uint32_t bl0 = Kl[srow * QSTR + base + tig];
            uint32_t bl1 = Kl[srow * QSTR + base + tig + 4];
            mma_bf16(s4, ah0, ah1, ah2, ah3, bh0, bh1);
            mma_bf16(s4, ah0, ah1, ah2, ah3, bl0, bl1);
            mma_bf16(s4, al0, al1, al2, al3, bh0, bh1);
        }
        {
            int col = kn + tig * 2;
            int r0 = qm + g, r1 = qm + g + 8;
            int sg0 = sc0 + col, sg1 = sg0 + 1;
            float v00 = s4[0], v01 = s4[1], v10 = s4[2], v11 = s4[3];
            if (sg0 > 4088 + (r0 & 7)) v00 = -10000.f;
            if (sg1 > 4088 + (r0 & 7)) v01 = -10000.f;
            if (sg0 > 4088 + (r1 & 7)) v10 = -10000.f;
            if (sg1 > 4088 + (r1 & 7)) v11 = -10000.f;
            Sc[r0 * SSTR + col] = v00; Sc[r0 * SSTR + col + 1] = v01;
            Sc[r1 * SSTR + col] = v10; Sc[r1 * SSTR + col + 1] = v11;
        }
        __syncthreads();

        // online softmax: warp w owns rows w*4 .. w*4+3 (32 cols each)
#pragma unroll
        for (int k2 = 0; k2 < 4; k2++) {
            int rr = w * 4 + k2;
            float v = Sc[rr * SSTR + lane];
            float mx = v;
#pragma unroll
            for (int off = 16; off > 0; off >>= 1)
                mx = fmaxf(mx, __shfl_xor_sync(0xffffffffu, mx, off));
            float mprev = rm[rr];
            float mnew = fmaxf(mprev, mx);
            float p = __expf(v - mnew);
            float ls = p;
#pragma unroll
            for (int off = 16; off > 0; off >>= 1)
                ls += __shfl_xor_sync(0xffffffffu, ls, off);
            float pe = __shfl_sync(0xffffffffu, p, (lane & 15) * 2);
            float po = __shfl_sync(0xffffffffu, p, (lane & 15) * 2 + 1);
            if (lane < 16) {
                uint32_t hh, ll;
                split2(pe, po, hh, ll);
                Ph[rr * PSTR + lane] = hh;
                Pl[rr * PSTR + lane] = ll;
            }
            if (lane == 0) {
                float f = __expf(mprev - mnew);
                rl[rr] = rl[rr] * f + ls;
                rm[rr] = mnew;
                rs[rr] = f;
            }
        }
        __syncthreads();

        // rescale + PV: warp computes 16 q-rows x 32 d-cols
        float f0 = rs[qm + g], f1 = rs[qm + g + 8];
#pragma unroll
        for (int nt = 0; nt < 4; nt++) {
            o[nt][0] *= f0; o[nt][1] *= f0;
            o[nt][2] *= f1; o[nt][3] *= f1;
        }
#pragma unroll
        for (int kstep = 0; kstep < 2; kstep++) {
            int base = kstep * 8;
            uint32_t ah0 = Ph[(qm + g) * PSTR + base + tig];
            uint32_t ah1 = Ph[(qm + g + 8) * PSTR + base + tig];
            uint32_t ah2 = Ph[(qm + g) * PSTR + base + tig + 4];
            uint32_t ah3 = Ph[(qm + g + 8) * PSTR + base + tig + 4];
            uint32_t al0 = Pl[(qm + g) * PSTR + base + tig];
            uint32_t al1 = Pl[(qm + g + 8) * PSTR + base + tig];
            uint32_t al2 = Pl[(qm + g) * PSTR + base + tig + 4];
            uint32_t al3 = Pl[(qm + g + 8) * PSTR + base + tig + 4];
#pragma unroll
            for (int nt = 0; nt < 4; nt++) {
                int drow = dB + nt * 8 + g;
                uint32_t bh0 = Vh[drow * VSTR + base + tig];
                uint32_t bh1 = Vh[drow * VSTR + base + tig + 4];
                uint32_t bl0 = Vl[drow * VSTR + base + tig];
                uint32_t bl1 = Vl[drow * VSTR + base + tig + 4];
                mma_bf16(o[nt], ah0, ah1, ah2, ah3, bh0, bh1);
                mma_bf16(o[nt], ah0, ah1, ah2, ah3, bl0, bl1);
                mma_bf16(o[nt], al0, al1, al2, al3, bh0, bh1);
            }
        }
    }

    int pbase = (bk * NSPLIT + sp) * 32;
    if (t < 32) { g_pm[pbase + t] = rm[t]; g_pl[pbase + t] = rl[t]; }
#pragma unroll
    for (int nt = 0; nt < 4; nt++) {
        int col = dB + nt * 8 + tig * 2;
        int r0 = qm + g, r1 = qm + g + 8;
        g_po[(size_t)(pbase + r0) * DH + col]     = o[nt][0];
        g_po[(size_t)(pbase + r0) * DH + col + 1] = o[nt][1];
        g_po[(size_t)(pbase + r1) * DH + col]     = o[nt][2];
        g_po[(size_t)(pbase + r1) * DH + col + 1] = o[nt][3];
    }
}

// ---------------------------------------------------------------------------
// Merge split partials (LSE) + relayout + pack directly as GEMM2's A operand.
// Each thread handles a d-pair (even,odd) -> one packed hi/lo u32.
// ---------------------------------------------------------------------------
__global__ void merge_kernel() {
    int i = blockIdx.x * 256 + threadIdx.x;   // 0 .. 131071
    int d2 = i & 63;                          // d pair index
    int rg = i >> 6;                          // bk*32 + r
    int bk = rg >> 5, r = rg & 31;
    int d = d2 * 2;
    float mv[NSPLIT];
    float mmax = -INFINITY;
#pragma unroll
    for (int sp = 0; sp < NSPLIT; sp++) {
        mv[sp] = g_pm[(bk * NSPLIT + sp) * 32 + r];
        mmax = fmaxf(mmax, mv[sp]);
    }
    float n0 = 0.f, n1 = 0.f, den = 0.f;
#pragma unroll
    for (int sp = 0; sp < NSPLIT; sp++) {
        float wgt = __expf(mv[sp] - mmax);
        size_t base = (size_t)((bk * NSPLIT + sp) * 32 + r) * DH + d;
        n0 += wgt * g_po[base];
        n1 += wgt * g_po[base + 1];
        den += wgt * g_pl[(bk * NSPLIT + sp) * 32 + r];
    }
    float inv = 1.f / den;
    float v0 = n0 * inv, v1 = n1 * inv;
    int b = bk >> 3, kvh = bk & 7, gg = r >> 3, qq = r & 7;
    int h = kvh * NG + gg;
    int m = b * NQ + qq;
    uint32_t hh, ll;
    split2(v0, v1, hh, ll);
    int idx = m * (HID / 2) + h * 64 + d2;
    g_ah[idx] = hh;
    g_al[idx] = ll;
}

// ---------------------------------------------------------------------------
// kernel_launch
// ---------------------------------------------------------------------------
extern "C" void kernel_launch(void* const* d_in, const int* in_sizes, int n_in,
                              void* d_out, int out_size) {
    (void)in_sizes; (void)n_in; (void)out_size;
    const float* hidden = (const float*)d_in[0];
    const int* pos = (const int*)d_in[1];
    const float* kc = (const float*)d_in[2];
    const float* vc = (const float*)d_in[3];
    const float* qw = (const float*)d_in[5];
    const float* ow = (const float*)d_in[6];
    float* out = (float*)d_out;

    static int attr_done = 0;
    if (!attr_done) {
        cudaFuncSetAttribute(attn_mma_kernel,
                             cudaFuncAttributeMaxDynamicSharedMemorySize,
                             SMEM_WORDS * 4);
        attr_done = 1;
    }

    rope_setup_kernel<<<1, 256>>>(pos);
    pack_a_kernel<<<256, 256>>>(hidden);
    gemm_mma_kernel<<<dim3(HID / 64, KSPLIT), 256>>>(qw);
    rope_reduce_kernel<<<512, 256>>>();
    attn_mma_kernel<<<64 * NSPLIT, 256, SMEM_WORDS * 4>>>(kc, vc);
    merge_kernel<<<512, 256>>>();
    gemm_mma_kernel<<<dim3(HID / 64, KSPLIT), 256>>>(ow);
    reduce_out_kernel<<<1024, 256>>>(out);
}